// round 1
// baseline (speedup 1.0000x reference)
#include <cuda_runtime.h>
#include <math.h>

// Problem constants
#define Bc      8
#define Nc      1024
#define Mc      512
#define Dc      128
#define HEADSc  8
#define Lc      6
#define DFFc    512
#define Sc      (Nc + Mc)      // 1536
#define HDc     16
#define MAXNB   64
#define ROWS    (Bc * Sc)      // 12288

// ---------------- scratch (device globals; no allocations allowed) ----------
__device__ float g_x  [ROWS * Dc];
__device__ float g_h  [ROWS * Dc];
__device__ float g_q  [ROWS * Dc];
__device__ float g_k  [ROWS * Dc];
__device__ float g_v  [ROWS * Dc];
__device__ float g_o  [ROWS * Dc];
__device__ float g_ffn[ROWS * DFFc];
__device__ float g_te [Bc * Dc];
__device__ float g_nodes[ROWS];
__device__ int   g_adj[Sc * MAXNB];
__device__ int   g_adjcnt[Sc];

// ---------------- init kernels ----------------------------------------------
__global__ void k_te(const int* __restrict__ t, const float* __restrict__ time_table) {
    int i = blockIdx.x * blockDim.x + threadIdx.x;
    if (i >= Bc * Dc) return;
    int b = i / Dc, d = i % Dc;
    g_te[i] = time_table[t[b] * Dc + d];
}

// nodes = [ |r_t| for variable nodes, syndrome parity for check nodes ]
__global__ void k_nodes(const float* __restrict__ r_t, const int* __restrict__ pcm) {
    int i = blockIdx.x * blockDim.x + threadIdx.x;
    if (i >= ROWS) return;
    int b = i / Sc, s = i % Sc;
    float val;
    if (s < Nc) {
        val = fabsf(r_t[b * Nc + s]);
    } else {
        int m = s - Nc;
        const int*   row = pcm + (size_t)m * Nc;
        const float* r   = r_t + (size_t)b * Nc;
        int par = 0;
        for (int n = 0; n < Nc; n++)
            if (row[n] != 0 && r[n] < 0.0f) par ^= 1;
        val = (float)par;
    }
    g_nodes[i] = val;
}

// adjacency: allowed attention keys per row (self + Tanner edges)
__global__ void k_adj(const int* __restrict__ pcm) {
    int s = blockIdx.x * blockDim.x + threadIdx.x;
    if (s >= Sc) return;
    int* adj = g_adj + s * MAXNB;
    int cnt = 0;
    adj[cnt++] = s;                 // diagonal of conn
    if (s < Nc) {
        for (int m = 0; m < Mc; m++)
            if (pcm[(size_t)m * Nc + s] != 0 && cnt < MAXNB) adj[cnt++] = Nc + m;
    } else {
        const int* row = pcm + (size_t)(s - Nc) * Nc;
        for (int n = 0; n < Nc; n++)
            if (row[n] != 0 && cnt < MAXNB) adj[cnt++] = n;
    }
    g_adjcnt[s] = cnt;
}

// x = te[b,:] * (src_embed[s,:] * nodes[b,s])
__global__ void k_xinit(const float* __restrict__ src_embed) {
    int i = blockIdx.x * blockDim.x + threadIdx.x;
    if (i >= ROWS * Dc) return;
    int d = i % Dc;
    int bs = i / Dc;
    int b = bs / Sc, s = bs % Sc;
    g_x[i] = src_embed[s * Dc + d] * g_nodes[bs] * g_te[b * Dc + d];
}

// ---------------- layernorm (block per row, 128 threads) ---------------------
__global__ void k_ln(const float* __restrict__ x, const float* __restrict__ gg,
                     const float* __restrict__ bb, int useTe, float* __restrict__ out) {
    int row = blockIdx.x;
    int tid = threadIdx.x;
    int b   = row / Sc;
    float v = x[(size_t)row * Dc + tid];

    float sum = v;
    #pragma unroll
    for (int o = 16; o > 0; o >>= 1) sum += __shfl_xor_sync(0xffffffffu, sum, o);
    __shared__ float sm[4];
    __shared__ float sm2[4];
    if ((tid & 31) == 0) sm[tid >> 5] = sum;
    __syncthreads();
    float mean = (sm[0] + sm[1] + sm[2] + sm[3]) * (1.0f / Dc);

    float dv = v - mean;
    float s2 = dv * dv;
    #pragma unroll
    for (int o = 16; o > 0; o >>= 1) s2 += __shfl_xor_sync(0xffffffffu, s2, o);
    if ((tid & 31) == 0) sm2[tid >> 5] = s2;
    __syncthreads();
    float var = (sm2[0] + sm2[1] + sm2[2] + sm2[3]) * (1.0f / Dc);

    float o2 = dv * rsqrtf(var + 1e-5f) * gg[tid] + bb[tid];
    if (useTe) o2 *= g_te[b * Dc + tid];
    out[(size_t)row * Dc + tid] = o2;
}

// ---------------- tiled SGEMM: C[M,N] (+)= A[M,K] @ B[K,N] -------------------
// MODE 0: store, MODE 1: residual add (C += acc), MODE 2: relu store
template <int MODE>
__global__ void k_gemm(const float* __restrict__ A, const float* __restrict__ Bm,
                       float* __restrict__ C, int K, int Nn) {
    __shared__ float As[16][65];   // As[k][m]
    __shared__ float Bs[16][64];   // Bs[k][n]
    int tid = threadIdx.x;
    int tx = tid & 15, ty = tid >> 4;
    int rowBase = blockIdx.y * 64, colBase = blockIdx.x * 64;

    float acc[4][4] = {};

    int aRow = tid >> 2, aCol = (tid & 3) * 4;
    int bRow = tid >> 4, bCol = (tid & 15) * 4;
    const float* Aptr = A + (size_t)(rowBase + aRow) * K + aCol;
    const float* Bptr = Bm + (size_t)bRow * Nn + colBase + bCol;

    for (int kt = 0; kt < K; kt += 16) {
        float4 av = *(const float4*)(Aptr + kt);
        As[aCol + 0][aRow] = av.x;
        As[aCol + 1][aRow] = av.y;
        As[aCol + 2][aRow] = av.z;
        As[aCol + 3][aRow] = av.w;
        float4 bv = *(const float4*)(Bptr + (size_t)kt * Nn);
        *(float4*)&Bs[bRow][bCol] = bv;
        __syncthreads();
        #pragma unroll
        for (int k = 0; k < 16; k++) {
            float ar[4], br[4];
            #pragma unroll
            for (int r = 0; r < 4; r++) ar[r] = As[k][ty * 4 + r];
            #pragma unroll
            for (int c = 0; c < 4; c++) br[c] = Bs[k][tx * 4 + c];
            #pragma unroll
            for (int r = 0; r < 4; r++)
                #pragma unroll
                for (int c = 0; c < 4; c++) acc[r][c] += ar[r] * br[c];
        }
        __syncthreads();
    }

    #pragma unroll
    for (int r = 0; r < 4; r++) {
        int row = rowBase + ty * 4 + r;
        float* cp = C + (size_t)row * Nn + colBase + tx * 4;
        #pragma unroll
        for (int c = 0; c < 4; c++) {
            float val = acc[r][c];
            if (MODE == 1)      cp[c] += val;
            else if (MODE == 2) cp[c] = fmaxf(val, 0.0f);
            else                cp[c] = val;
        }
    }
}

// ---------------- sparse masked attention ------------------------------------
// block = one (b,s) row, 8 warps = 8 heads; lanes cover up to 64 neighbors.
__global__ void k_attn(const float* __restrict__ q, const float* __restrict__ k,
                       const float* __restrict__ v, float* __restrict__ o) {
    int bs = blockIdx.x;
    int b = bs / Sc, s = bs % Sc;
    int h = threadIdx.x >> 5, lane = threadIdx.x & 31;
    int cnt = g_adjcnt[s];

    const float* qp = q + (size_t)bs * Dc + h * HDc;
    float qr[HDc];
    #pragma unroll
    for (int d = 0; d < HDc; d++) qr[d] = qp[d];

    float sc0 = -1e30f, sc1 = -1e30f;
    int n0 = -1, n1 = -1;
    if (lane < cnt) {
        n0 = g_adj[s * MAXNB + lane];
        const float* kp = k + ((size_t)b * Sc + n0) * Dc + h * HDc;
        float dot = 0.0f;
        #pragma unroll
        for (int d = 0; d < HDc; d++) dot += qr[d] * kp[d];
        sc0 = dot * 0.25f;   // 1/sqrt(16)
    }
    if (lane + 32 < cnt) {
        n1 = g_adj[s * MAXNB + lane + 32];
        const float* kp = k + ((size_t)b * Sc + n1) * Dc + h * HDc;
        float dot = 0.0f;
        #pragma unroll
        for (int d = 0; d < HDc; d++) dot += qr[d] * kp[d];
        sc1 = dot * 0.25f;
    }

    float m = fmaxf(sc0, sc1);
    #pragma unroll
    for (int off = 16; off > 0; off >>= 1) m = fmaxf(m, __shfl_xor_sync(0xffffffffu, m, off));

    float p0 = (n0 >= 0) ? __expf(sc0 - m) : 0.0f;
    float p1 = (n1 >= 0) ? __expf(sc1 - m) : 0.0f;
    float ps = p0 + p1;
    #pragma unroll
    for (int off = 16; off > 0; off >>= 1) ps += __shfl_xor_sync(0xffffffffu, ps, off);

    float acc[HDc] = {};
    if (n0 >= 0) {
        const float* vp = v + ((size_t)b * Sc + n0) * Dc + h * HDc;
        #pragma unroll
        for (int d = 0; d < HDc; d++) acc[d] += p0 * vp[d];
    }
    if (n1 >= 0) {
        const float* vp = v + ((size_t)b * Sc + n1) * Dc + h * HDc;
        #pragma unroll
        for (int d = 0; d < HDc; d++) acc[d] += p1 * vp[d];
    }
    #pragma unroll
    for (int d = 0; d < HDc; d++) {
        #pragma unroll
        for (int off = 16; off > 0; off >>= 1)
            acc[d] += __shfl_xor_sync(0xffffffffu, acc[d], off);
    }
    if (lane == 0) {
        float inv = 1.0f / ps;
        float* op = o + (size_t)bs * Dc + h * HDc;
        #pragma unroll
        for (int d = 0; d < HDc; d++) op[d] = acc[d] * inv;
    }
}

// ---------------- final projection: out[b,s] = x . fc_w + fc_b ---------------
__global__ void k_out(const float* __restrict__ fc_w, const float* __restrict__ fc_b,
                      float* __restrict__ out) {
    int row = blockIdx.x * 8 + (threadIdx.x >> 5);
    if (row >= ROWS) return;
    int lane = threadIdx.x & 31;
    float sum = 0.0f;
    #pragma unroll
    for (int d = lane; d < Dc; d += 32) sum += g_x[(size_t)row * Dc + d] * fc_w[d];
    #pragma unroll
    for (int off = 16; off > 0; off >>= 1) sum += __shfl_xor_sync(0xffffffffu, sum, off);
    if (lane == 0) out[row] = sum + fc_b[0];
}

// ---------------- launcher ---------------------------------------------------
extern "C" void kernel_launch(void* const* d_in, const int* in_sizes, int n_in,
                              void* d_out, int out_size) {
    const float* r_t        = (const float*)d_in[0];
    const int*   t          = (const int*)  d_in[1];
    const int*   pcm        = (const int*)  d_in[2];
    /* d_in[3] = mask (bool) — recomputed from pcm, ignored */
    const float* src_embed  = (const float*)d_in[4];
    const float* time_table = (const float*)d_in[5];
    const float* Wq = (const float*)d_in[6];
    const float* Wk = (const float*)d_in[7];
    const float* Wv = (const float*)d_in[8];
    const float* Wo = (const float*)d_in[9];
    const float* W1 = (const float*)d_in[10];
    const float* W2 = (const float*)d_in[11];
    const float* g1 = (const float*)d_in[12];
    const float* b1 = (const float*)d_in[13];
    const float* g2 = (const float*)d_in[14];
    const float* b2 = (const float*)d_in[15];
    const float* fc_w = (const float*)d_in[16];
    const float* fc_b = (const float*)d_in[17];
    float* out = (float*)d_out;

    float *px, *ph, *pq, *pk, *pv, *po, *pffn;
    cudaGetSymbolAddress((void**)&px,   g_x);
    cudaGetSymbolAddress((void**)&ph,   g_h);
    cudaGetSymbolAddress((void**)&pq,   g_q);
    cudaGetSymbolAddress((void**)&pk,   g_k);
    cudaGetSymbolAddress((void**)&pv,   g_v);
    cudaGetSymbolAddress((void**)&po,   g_o);
    cudaGetSymbolAddress((void**)&pffn, g_ffn);

    k_te   <<<(Bc * Dc + 255) / 256, 256>>>(t, time_table);
    k_nodes<<<(ROWS + 255) / 256, 256>>>(r_t, pcm);
    k_adj  <<<(Sc + 127) / 128, 128>>>(pcm);
    k_xinit<<<(ROWS * Dc + 255) / 256, 256>>>(src_embed);

    dim3 gD(Dc / 64, ROWS / 64);     // (2, 192)   N=128 GEMMs
    dim3 gF(DFFc / 64, ROWS / 64);   // (8, 192)   N=512 GEMM

    for (int l = 0; l < Lc; l++) {
        const float* wq = Wq + (size_t)l * Dc * Dc;
        const float* wk = Wk + (size_t)l * Dc * Dc;
        const float* wv = Wv + (size_t)l * Dc * Dc;
        const float* wo = Wo + (size_t)l * Dc * Dc;
        const float* w1 = W1 + (size_t)l * Dc * DFFc;
        const float* w2 = W2 + (size_t)l * DFFc * Dc;

        k_ln<<<ROWS, 128>>>(px, g1 + l * Dc, b1 + l * Dc, 0, ph);
        k_gemm<0><<<gD, 256>>>(ph, wq, pq, Dc, Dc);
        k_gemm<0><<<gD, 256>>>(ph, wk, pk, Dc, Dc);
        k_gemm<0><<<gD, 256>>>(ph, wv, pv, Dc, Dc);
        k_attn<<<ROWS, 256>>>(pq, pk, pv, po);
        k_gemm<1><<<gD, 256>>>(po, wo, px, Dc, Dc);          // x += o @ Wo

        k_ln<<<ROWS, 128>>>(px, g2 + l * Dc, b2 + l * Dc, 1, ph);  // FiLM: * te
        k_gemm<2><<<gF, 256>>>(ph, w1, pffn, Dc, DFFc);       // relu(h2 @ W1)
        k_gemm<1><<<gD, 256>>>(pffn, w2, px, DFFc, Dc);       // x += ffn @ W2
    }

    k_out<<<(ROWS + 7) / 8, 256>>>(fc_w, fc_b, out);
}

// round 2
// speedup vs baseline: 1.3145x; 1.3145x over previous
#include <cuda_runtime.h>
#include <cuda_bf16.h>
#include <math.h>

// Problem constants
#define Bc      8
#define Nc      1024
#define Mc      512
#define Dc      128
#define HEADSc  8
#define Lc      6
#define DFFc    512
#define Sc      (Nc + Mc)      // 1536
#define HDc     16
#define MAXNB   64
#define ROWS    (Bc * Sc)      // 12288
#define PER_L   196608         // packed transposed weights per layer (bf16 elems)

// ---------------- scratch (device globals) -----------------------------------
__device__ float g_x  [ROWS * Dc];
__device__ float g_qkv[ROWS * 384];
__device__ float g_te [Bc * Dc];
__device__ float g_nodes[ROWS];
__device__ int   g_adj[Sc * MAXNB];
__device__ int   g_adjcnt[Sc];

__device__ __nv_bfloat16 g_wThi[Lc * PER_L];
__device__ __nv_bfloat16 g_wTlo[Lc * PER_L];
__device__ __nv_bfloat16 g_hhi[ROWS * Dc];
__device__ __nv_bfloat16 g_hlo[ROWS * Dc];
__device__ __nv_bfloat16 g_ohi[ROWS * Dc];
__device__ __nv_bfloat16 g_olo[ROWS * Dc];
__device__ __nv_bfloat16 g_fhi[ROWS * DFFc];
__device__ __nv_bfloat16 g_flo[ROWS * DFFc];

__device__ __forceinline__ void split_bf16(float v, __nv_bfloat16& hi, __nv_bfloat16& lo) {
    hi = __float2bfloat16_rn(v);
    lo = __float2bfloat16_rn(v - __bfloat162float(hi));
}

// ---------------- init kernels ------------------------------------------------
__global__ void k_te(const int* __restrict__ t, const float* __restrict__ time_table) {
    int i = blockIdx.x * blockDim.x + threadIdx.x;
    if (i >= Bc * Dc) return;
    int b = i / Dc, d = i % Dc;
    g_te[i] = time_table[t[b] * Dc + d];
}

__global__ void k_nodes(const float* __restrict__ r_t, const int* __restrict__ pcm) {
    int i = blockIdx.x * blockDim.x + threadIdx.x;
    if (i >= ROWS) return;
    int b = i / Sc, s = i % Sc;
    float val;
    if (s < Nc) {
        val = fabsf(r_t[b * Nc + s]);
    } else {
        int m = s - Nc;
        const int*   row = pcm + (size_t)m * Nc;
        const float* r   = r_t + (size_t)b * Nc;
        int par = 0;
        for (int n = 0; n < Nc; n++)
            if (row[n] != 0 && r[n] < 0.0f) par ^= 1;
        val = (float)par;
    }
    g_nodes[i] = val;
}

__global__ void k_adj(const int* __restrict__ pcm) {
    int s = blockIdx.x * blockDim.x + threadIdx.x;
    if (s >= Sc) return;
    int* adj = g_adj + s * MAXNB;
    int cnt = 0;
    adj[cnt++] = s;
    if (s < Nc) {
        for (int m = 0; m < Mc; m++)
            if (pcm[(size_t)m * Nc + s] != 0 && cnt < MAXNB) adj[cnt++] = Nc + m;
    } else {
        const int* row = pcm + (size_t)(s - Nc) * Nc;
        for (int n = 0; n < Nc; n++)
            if (row[n] != 0 && cnt < MAXNB) adj[cnt++] = n;
    }
    g_adjcnt[s] = cnt;
}

__global__ void k_xinit(const float* __restrict__ src_embed) {
    int i = blockIdx.x * blockDim.x + threadIdx.x;
    if (i >= ROWS * Dc) return;
    int d = i % Dc;
    int bs = i / Dc;
    int b = bs / Sc, s = bs % Sc;
    g_x[i] = src_embed[s * Dc + d] * g_nodes[bs] * g_te[b * Dc + d];
}

// weight split + transpose into packed per-layer layout (bf16 hi/lo):
//   [0,49152):      QKV^T  rows n'=0..383 (Wq,Wk,Wv), [n'][k], K=128
//   [49152,65536):  Wo^T   [n][k], K=128
//   [65536,131072): W1^T   512 rows x 128
//   [131072,196608):W2^T   128 rows x 512
__global__ void k_wsplit(const float* __restrict__ Wq, const float* __restrict__ Wk,
                         const float* __restrict__ Wv, const float* __restrict__ Wo,
                         const float* __restrict__ W1, const float* __restrict__ W2) {
    int idx = blockIdx.x * blockDim.x + threadIdx.x;
    if (idx >= Lc * PER_L) return;
    int l = idx / PER_L, off = idx % PER_L;
    float v;
    if (off < 49152) {
        int w = off >> 14;
        int r = off & 16383;
        int n = r >> 7, k = r & 127;
        const float* W = (w == 0) ? Wq : (w == 1) ? Wk : Wv;
        v = W[(size_t)l * 16384 + k * 128 + n];
    } else if (off < 65536) {
        int r = off - 49152;
        int n = r >> 7, k = r & 127;
        v = Wo[(size_t)l * 16384 + k * 128 + n];
    } else if (off < 131072) {
        int r = off - 65536;
        int n = r >> 7, k = r & 127;
        v = W1[(size_t)l * 65536 + k * 512 + n];
    } else {
        int r = off - 131072;
        int n = r >> 9, k = r & 511;
        v = W2[(size_t)l * 65536 + k * 128 + n];
    }
    __nv_bfloat16 hi, lo;
    split_bf16(v, hi, lo);
    g_wThi[idx] = hi;
    g_wTlo[idx] = lo;
}

// ---------------- layernorm -> split bf16 output ------------------------------
__global__ void k_ln(const float* __restrict__ x, const float* __restrict__ gg,
                     const float* __restrict__ bb, int useTe,
                     __nv_bfloat16* __restrict__ hhi, __nv_bfloat16* __restrict__ hlo) {
    int row = blockIdx.x;
    int tid = threadIdx.x;
    int b   = row / Sc;
    float v = x[(size_t)row * Dc + tid];

    float sum = v;
    #pragma unroll
    for (int o = 16; o > 0; o >>= 1) sum += __shfl_xor_sync(0xffffffffu, sum, o);
    __shared__ float sm[4];
    __shared__ float sm2[4];
    if ((tid & 31) == 0) sm[tid >> 5] = sum;
    __syncthreads();
    float mean = (sm[0] + sm[1] + sm[2] + sm[3]) * (1.0f / Dc);

    float dv = v - mean;
    float s2 = dv * dv;
    #pragma unroll
    for (int o = 16; o > 0; o >>= 1) s2 += __shfl_xor_sync(0xffffffffu, s2, o);
    if ((tid & 31) == 0) sm2[tid >> 5] = s2;
    __syncthreads();
    float var = (sm2[0] + sm2[1] + sm2[2] + sm2[3]) * (1.0f / Dc);

    float o2 = dv * rsqrtf(var + 1e-5f) * gg[tid] + bb[tid];
    if (useTe) o2 *= g_te[b * Dc + tid];
    __nv_bfloat16 hi, lo;
    split_bf16(o2, hi, lo);
    hhi[(size_t)row * Dc + tid] = hi;
    hlo[(size_t)row * Dc + tid] = lo;
}

// ---------------- bf16x3 tensor-core GEMM -------------------------------------
// C[M,Nn] (+)= (Ahi+Alo)[M,K] @ (Bhi+Blo)^T   where B stored [Nn][K] (n-major)
// MODE 0: store f32, MODE 1: residual add f32, MODE 3: relu -> split bf16 store
#define BM 128
#define BN 64
#define BK 32

__device__ __forceinline__ void mma_bf16(float* c, const unsigned* a, const unsigned* b) {
    asm volatile(
        "mma.sync.aligned.m16n8k16.row.col.f32.bf16.bf16.f32 "
        "{%0,%1,%2,%3}, {%4,%5,%6,%7}, {%8,%9}, {%0,%1,%2,%3};"
        : "+f"(c[0]), "+f"(c[1]), "+f"(c[2]), "+f"(c[3])
        : "r"(a[0]), "r"(a[1]), "r"(a[2]), "r"(a[3]), "r"(b[0]), "r"(b[1]));
}

template <int MODE>
__global__ void __launch_bounds__(256)
k_gemm(const __nv_bfloat16* __restrict__ Ahi, const __nv_bfloat16* __restrict__ Alo,
       const __nv_bfloat16* __restrict__ Bhi, const __nv_bfloat16* __restrict__ Blo,
       float* __restrict__ C,
       __nv_bfloat16* __restrict__ Chi, __nv_bfloat16* __restrict__ Clo,
       int K, int Nn) {
    // padded word stride 20 (40 bf16) -> conflict-free 32-bit frag loads
    __shared__ __align__(16) __nv_bfloat16 sA[2][BM * 40];
    __shared__ __align__(16) __nv_bfloat16 sB[2][BN * 40];

    const int tid = threadIdx.x;
    const int lane = tid & 31, warp = tid >> 5;
    const int wm = (warp & 3) * 32, wn = (warp >> 2) * 32;
    const int g = lane >> 2, q4 = lane & 3;
    const int rowBase = blockIdx.y * BM, colBase = blockIdx.x * BN;

    float acc[2][4][4];
    #pragma unroll
    for (int mt = 0; mt < 2; mt++)
        #pragma unroll
        for (int nt = 0; nt < 4; nt++)
            #pragma unroll
            for (int i = 0; i < 4; i++) acc[mt][nt][i] = 0.0f;

    const unsigned* wA0 = (const unsigned*)sA[0];
    const unsigned* wA1 = (const unsigned*)sA[1];
    const unsigned* wB0 = (const unsigned*)sB[0];
    const unsigned* wB1 = (const unsigned*)sB[1];

    for (int kt = 0; kt < K; kt += BK) {
        // A tile: 128 x 32, 2 x uint4 per thread per buffer
        #pragma unroll
        for (int i = 0; i < 2; i++) {
            int idx = tid + i * 256;
            int r = idx >> 2, c4 = idx & 3;
            size_t goff = (size_t)(rowBase + r) * K + kt + c4 * 8;
            *(uint4*)&sA[0][r * 40 + c4 * 8] = *(const uint4*)(Ahi + goff);
            *(uint4*)&sA[1][r * 40 + c4 * 8] = *(const uint4*)(Alo + goff);
        }
        // B tile: 64 x 32 (n-major), 1 x uint4 per thread per buffer
        {
            int n = tid >> 2, c4 = tid & 3;
            size_t goff = (size_t)(colBase + n) * K + kt + c4 * 8;
            *(uint4*)&sB[0][n * 40 + c4 * 8] = *(const uint4*)(Bhi + goff);
            *(uint4*)&sB[1][n * 40 + c4 * 8] = *(const uint4*)(Blo + goff);
        }
        __syncthreads();

        #pragma unroll
        for (int kk = 0; kk < 2; kk++) {
            unsigned ah[2][4], al[2][4], bh[4][2], bl[4][2];
            #pragma unroll
            for (int mt = 0; mt < 2; mt++) {
                int r0 = wm + mt * 16 + g;
                int w0 = kk * 8 + q4;
                ah[mt][0] = wA0[r0 * 20 + w0];
                ah[mt][1] = wA0[(r0 + 8) * 20 + w0];
                ah[mt][2] = wA0[r0 * 20 + w0 + 4];
                ah[mt][3] = wA0[(r0 + 8) * 20 + w0 + 4];
                al[mt][0] = wA1[r0 * 20 + w0];
                al[mt][1] = wA1[(r0 + 8) * 20 + w0];
                al[mt][2] = wA1[r0 * 20 + w0 + 4];
                al[mt][3] = wA1[(r0 + 8) * 20 + w0 + 4];
            }
            #pragma unroll
            for (int nt = 0; nt < 4; nt++) {
                int n0 = wn + nt * 8 + g;
                int w0 = kk * 8 + q4;
                bh[nt][0] = wB0[n0 * 20 + w0];
                bh[nt][1] = wB0[n0 * 20 + w0 + 4];
                bl[nt][0] = wB1[n0 * 20 + w0];
                bl[nt][1] = wB1[n0 * 20 + w0 + 4];
            }
            #pragma unroll
            for (int mt = 0; mt < 2; mt++)
                #pragma unroll
                for (int nt = 0; nt < 4; nt++) {
                    mma_bf16(acc[mt][nt], ah[mt], bh[nt]);
                    mma_bf16(acc[mt][nt], ah[mt], bl[nt]);
                    mma_bf16(acc[mt][nt], al[mt], bh[nt]);
                }
        }
        __syncthreads();
    }

    // epilogue
    #pragma unroll
    for (int mt = 0; mt < 2; mt++)
        #pragma unroll
        for (int nt = 0; nt < 4; nt++) {
            int r = rowBase + wm + mt * 16 + g;
            int c = colBase + wn + nt * 8 + q4 * 2;
            float* a = acc[mt][nt];
            if (MODE == 0) {
                *(float2*)&C[(size_t)r * Nn + c]       = make_float2(a[0], a[1]);
                *(float2*)&C[(size_t)(r + 8) * Nn + c] = make_float2(a[2], a[3]);
            } else if (MODE == 1) {
                float2 v0 = *(const float2*)&C[(size_t)r * Nn + c];
                float2 v1 = *(const float2*)&C[(size_t)(r + 8) * Nn + c];
                v0.x += a[0]; v0.y += a[1]; v1.x += a[2]; v1.y += a[3];
                *(float2*)&C[(size_t)r * Nn + c]       = v0;
                *(float2*)&C[(size_t)(r + 8) * Nn + c] = v1;
            } else {
                #pragma unroll
                for (int rr = 0; rr < 2; rr++) {
                    float v0 = fmaxf(a[rr * 2 + 0], 0.0f);
                    float v1 = fmaxf(a[rr * 2 + 1], 0.0f);
                    __nv_bfloat16 h0, l0, h1, l1;
                    split_bf16(v0, h0, l0);
                    split_bf16(v1, h1, l1);
                    __nv_bfloat162 hh; hh.x = h0; hh.y = h1;
                    __nv_bfloat162 ll; ll.x = l0; ll.y = l1;
                    size_t o = (size_t)(r + rr * 8) * Nn + c;
                    *(__nv_bfloat162*)&Chi[o] = hh;
                    *(__nv_bfloat162*)&Clo[o] = ll;
                }
            }
        }
}

// ---------------- sparse masked attention (packed qkv, stride 384) ------------
__global__ void k_attn(const float* __restrict__ qkv,
                       __nv_bfloat16* __restrict__ ohi, __nv_bfloat16* __restrict__ olo) {
    int bs = blockIdx.x;
    int b = bs / Sc, s = bs % Sc;
    int h = threadIdx.x >> 5, lane = threadIdx.x & 31;
    int cnt = g_adjcnt[s];

    const float* qp = qkv + (size_t)bs * 384 + h * HDc;
    float qr[HDc];
    #pragma unroll
    for (int d = 0; d < HDc; d++) qr[d] = qp[d];

    float sc0 = -1e30f, sc1 = -1e30f;
    int n0 = -1, n1 = -1;
    if (lane < cnt) {
        n0 = g_adj[s * MAXNB + lane];
        const float* kp = qkv + ((size_t)b * Sc + n0) * 384 + 128 + h * HDc;
        float dot = 0.0f;
        #pragma unroll
        for (int d = 0; d < HDc; d++) dot += qr[d] * kp[d];
        sc0 = dot * 0.25f;
    }
    if (lane + 32 < cnt) {
        n1 = g_adj[s * MAXNB + lane + 32];
        const float* kp = qkv + ((size_t)b * Sc + n1) * 384 + 128 + h * HDc;
        float dot = 0.0f;
        #pragma unroll
        for (int d = 0; d < HDc; d++) dot += qr[d] * kp[d];
        sc1 = dot * 0.25f;
    }

    float m = fmaxf(sc0, sc1);
    #pragma unroll
    for (int off = 16; off > 0; off >>= 1) m = fmaxf(m, __shfl_xor_sync(0xffffffffu, m, off));

    float p0 = (n0 >= 0) ? __expf(sc0 - m) : 0.0f;
    float p1 = (n1 >= 0) ? __expf(sc1 - m) : 0.0f;
    float ps = p0 + p1;
    #pragma unroll
    for (int off = 16; off > 0; off >>= 1) ps += __shfl_xor_sync(0xffffffffu, ps, off);

    float acc[HDc] = {};
    if (n0 >= 0) {
        const float* vp = qkv + ((size_t)b * Sc + n0) * 384 + 256 + h * HDc;
        #pragma unroll
        for (int d = 0; d < HDc; d++) acc[d] += p0 * vp[d];
    }
    if (n1 >= 0) {
        const float* vp = qkv + ((size_t)b * Sc + n1) * 384 + 256 + h * HDc;
        #pragma unroll
        for (int d = 0; d < HDc; d++) acc[d] += p1 * vp[d];
    }
    #pragma unroll
    for (int d = 0; d < HDc; d++) {
        #pragma unroll
        for (int off = 16; off > 0; off >>= 1)
            acc[d] += __shfl_xor_sync(0xffffffffu, acc[d], off);
    }
    if (lane == 0) {
        float inv = 1.0f / ps;
        #pragma unroll
        for (int d = 0; d < HDc; d++) {
            float val = acc[d] * inv;
            __nv_bfloat16 hi, lo;
            split_bf16(val, hi, lo);
            ohi[(size_t)bs * Dc + h * HDc + d] = hi;
            olo[(size_t)bs * Dc + h * HDc + d] = lo;
        }
    }
}

// ---------------- final projection --------------------------------------------
__global__ void k_out(const float* __restrict__ fc_w, const float* __restrict__ fc_b,
                      float* __restrict__ out) {
    int row = blockIdx.x * 8 + (threadIdx.x >> 5);
    if (row >= ROWS) return;
    int lane = threadIdx.x & 31;
    float sum = 0.0f;
    #pragma unroll
    for (int d = lane; d < Dc; d += 32) sum += g_x[(size_t)row * Dc + d] * fc_w[d];
    #pragma unroll
    for (int off = 16; off > 0; off >>= 1) sum += __shfl_xor_sync(0xffffffffu, sum, off);
    if (lane == 0) out[row] = sum + fc_b[0];
}

// ---------------- launcher -----------------------------------------------------
extern "C" void kernel_launch(void* const* d_in, const int* in_sizes, int n_in,
                              void* d_out, int out_size) {
    const float* r_t        = (const float*)d_in[0];
    const int*   t          = (const int*)  d_in[1];
    const int*   pcm        = (const int*)  d_in[2];
    const float* src_embed  = (const float*)d_in[4];
    const float* time_table = (const float*)d_in[5];
    const float* Wq = (const float*)d_in[6];
    const float* Wk = (const float*)d_in[7];
    const float* Wv = (const float*)d_in[8];
    const float* Wo = (const float*)d_in[9];
    const float* W1 = (const float*)d_in[10];
    const float* W2 = (const float*)d_in[11];
    const float* g1 = (const float*)d_in[12];
    const float* b1 = (const float*)d_in[13];
    const float* g2 = (const float*)d_in[14];
    const float* b2 = (const float*)d_in[15];
    const float* fc_w = (const float*)d_in[16];
    const float* fc_b = (const float*)d_in[17];
    float* out = (float*)d_out;

    float *px, *pqkv;
    __nv_bfloat16 *whi, *wlo, *hhi, *hlo, *ohi, *olo, *fhi, *flo;
    cudaGetSymbolAddress((void**)&px,   g_x);
    cudaGetSymbolAddress((void**)&pqkv, g_qkv);
    cudaGetSymbolAddress((void**)&whi,  g_wThi);
    cudaGetSymbolAddress((void**)&wlo,  g_wTlo);
    cudaGetSymbolAddress((void**)&hhi,  g_hhi);
    cudaGetSymbolAddress((void**)&hlo,  g_hlo);
    cudaGetSymbolAddress((void**)&ohi,  g_ohi);
    cudaGetSymbolAddress((void**)&olo,  g_olo);
    cudaGetSymbolAddress((void**)&fhi,  g_fhi);
    cudaGetSymbolAddress((void**)&flo,  g_flo);

    k_te    <<<(Bc * Dc + 255) / 256, 256>>>(t, time_table);
    k_nodes <<<(ROWS + 255) / 256, 256>>>(r_t, pcm);
    k_adj   <<<(Sc + 127) / 128, 128>>>(pcm);
    k_xinit <<<(ROWS * Dc + 255) / 256, 256>>>(src_embed);
    k_wsplit<<<(Lc * PER_L + 255) / 256, 256>>>(Wq, Wk, Wv, Wo, W1, W2);

    dim3 gQKV(384 / BN, ROWS / BM);   // (6, 96)
    dim3 gD  (128 / BN, ROWS / BM);   // (2, 96)
    dim3 gF  (512 / BN, ROWS / BM);   // (8, 96)

    for (int l = 0; l < Lc; l++) {
        const __nv_bfloat16* lwh = whi + (size_t)l * PER_L;
        const __nv_bfloat16* lwl = wlo + (size_t)l * PER_L;

        k_ln<<<ROWS, 128>>>(px, g1 + l * Dc, b1 + l * Dc, 0, hhi, hlo);
        k_gemm<0><<<gQKV, 256>>>(hhi, hlo, lwh, lwl, pqkv, nullptr, nullptr, 128, 384);
        k_attn<<<ROWS, 256>>>(pqkv, ohi, olo);
        k_gemm<1><<<gD, 256>>>(ohi, olo, lwh + 49152, lwl + 49152, px, nullptr, nullptr, 128, 128);

        k_ln<<<ROWS, 128>>>(px, g2 + l * Dc, b2 + l * Dc, 1, hhi, hlo);
        k_gemm<3><<<gF, 256>>>(hhi, hlo, lwh + 65536, lwl + 65536, nullptr, fhi, flo, 128, 512);
        k_gemm<1><<<gD, 256>>>(fhi, flo, lwh + 131072, lwl + 131072, px, nullptr, nullptr, 512, 128);
    }

    k_out<<<(ROWS + 7) / 8, 256>>>(fc_w, fc_b, out);
}

// round 3
// speedup vs baseline: 1.6486x; 1.2541x over previous
#include <cuda_runtime.h>
#include <cuda_bf16.h>
#include <math.h>

#define Bc      8
#define Nc      1024
#define Mc      512
#define Dc      128
#define Lc      6
#define DFFc    512
#define Sc      (Nc + Mc)      // 1536
#define HDc     16
#define MAXNB   64
#define ROWS    (Bc * Sc)      // 12288
#define PER_L   196608         // packed transposed weights per layer

// ---------------- scratch ------------------------------------------------------
__device__ float g_x  [ROWS * Dc];
__device__ float g_qkv[ROWS * 384];
__device__ float g_te [Bc * Dc];
__device__ float g_nodes[ROWS];
__device__ int   g_adj[Sc * MAXNB];
__device__ int   g_adjcnt[Sc];

__device__ __nv_bfloat16 g_wThi[Lc * PER_L];
__device__ __nv_bfloat16 g_wTlo[Lc * PER_L];
__device__ __nv_bfloat16 g_ohi[ROWS * Dc];
__device__ __nv_bfloat16 g_olo[ROWS * Dc];
__device__ __nv_bfloat16 g_fhi[ROWS * DFFc];
__device__ __nv_bfloat16 g_flo[ROWS * DFFc];

__device__ __forceinline__ void split_bf16(float v, __nv_bfloat16& hi, __nv_bfloat16& lo) {
    hi = __float2bfloat16_rn(v);
    lo = __float2bfloat16_rn(v - __bfloat162float(hi));
}
__device__ __forceinline__ unsigned pack2hi(float a, float b) {
    __nv_bfloat162 p; p.x = __float2bfloat16_rn(a); p.y = __float2bfloat16_rn(b);
    return *(unsigned*)&p;
}
__device__ __forceinline__ unsigned pack2lo(float a, float b) {
    __nv_bfloat162 p;
    p.x = __float2bfloat16_rn(a - __bfloat162float(__float2bfloat16_rn(a)));
    p.y = __float2bfloat16_rn(b - __bfloat162float(__float2bfloat16_rn(b)));
    return *(unsigned*)&p;
}

// ---------------- init ----------------------------------------------------------
__global__ void k_te(const int* __restrict__ t, const float* __restrict__ time_table) {
    int i = blockIdx.x * blockDim.x + threadIdx.x;
    if (i >= Bc * Dc) return;
    int b = i / Dc, d = i % Dc;
    g_te[i] = time_table[t[b] * Dc + d];
}

// syndrome parity for check nodes: warp per (b, m), ballot popcount
__global__ void k_nodes(const float* __restrict__ r_t, const int* __restrict__ pcm) {
    int w = blockIdx.x * 8 + (threadIdx.x >> 5);
    if (w >= Bc * Mc) return;
    int lane = threadIdx.x & 31;
    int b = w >> 9, m = w & 511;
    int cnt = 0;
    #pragma unroll
    for (int i = 0; i < 32; i++) {
        int col = lane + i * 32;
        bool pred = (pcm[(size_t)m * Nc + col] != 0) && (r_t[(size_t)b * Nc + col] < 0.0f);
        cnt += __popc(__ballot_sync(0xffffffffu, pred));
    }
    if (lane == 0) g_nodes[(size_t)b * Sc + Nc + m] = (float)(cnt & 1);
}

// adjacency via warp ballot compaction
__global__ void k_adj(const int* __restrict__ pcm) {
    int s = blockIdx.x * 8 + (threadIdx.x >> 5);
    if (s >= Sc) return;
    int lane = threadIdx.x & 31;
    unsigned lt = (1u << lane) - 1u;
    int* adj = g_adj + s * MAXNB;
    int cnt = 1;
    if (lane == 0) adj[0] = s;
    if (s < Nc) {
        #pragma unroll
        for (int i = 0; i < 16; i++) {
            int m = lane + i * 32;
            bool pred = pcm[(size_t)m * Nc + s] != 0;
            unsigned bal = __ballot_sync(0xffffffffu, pred);
            int rank = __popc(bal & lt);
            if (pred && cnt + rank < MAXNB) adj[cnt + rank] = Nc + m;
            cnt += __popc(bal);
        }
    } else {
        const int* row = pcm + (size_t)(s - Nc) * Nc;
        #pragma unroll
        for (int i = 0; i < 32; i++) {
            int n = lane + i * 32;
            bool pred = row[n] != 0;
            unsigned bal = __ballot_sync(0xffffffffu, pred);
            int rank = __popc(bal & lt);
            if (pred && cnt + rank < MAXNB) adj[cnt + rank] = n;
            cnt += __popc(bal);
        }
    }
    if (lane == 0) g_adjcnt[s] = cnt < MAXNB ? cnt : MAXNB;
}

__global__ void k_xinit(const float* __restrict__ src_embed, const float* __restrict__ r_t) {
    int i = blockIdx.x * blockDim.x + threadIdx.x;
    if (i >= ROWS * Dc) return;
    int d = i % Dc;
    int bs = i / Dc;
    int b = bs / Sc, s = bs % Sc;
    float node = (s < Nc) ? fabsf(r_t[(size_t)b * Nc + s]) : g_nodes[bs];
    g_x[i] = src_embed[s * Dc + d] * node * g_te[b * Dc + d];
}

// ---------------- weight transpose+split (coalesced, 32x32 tiles) ---------------
// dst layout per layer: [0,49152) QKV^T [n'=0..383][k=0..127]
//                       [49152,65536) Wo^T [n][k]
//                       [65536,131072) W1^T [n=0..511][k]
//                       [131072,196608) W2^T [n=0..127][k=0..511]
__global__ void k_wsplit(const float* __restrict__ Wq, const float* __restrict__ Wk,
                         const float* __restrict__ Wv, const float* __restrict__ Wo,
                         const float* __restrict__ W1, const float* __restrict__ W2) {
    __shared__ float s[32][33];
    int bid = blockIdx.x;
    int l = bid / 192, tt = bid % 192;
    const float* src; int Nn, k0, n0; size_t dstBase; int dstLd;
    if (tt < 64) {
        int seg = tt >> 4, local = tt & 15;
        int tk = local >> 2, tn = local & 3;
        k0 = tk * 32; n0 = tn * 32; Nn = 128; dstLd = 128;
        if      (seg == 0) { src = Wq + (size_t)l * 16384; dstBase = (size_t)l * PER_L; }
        else if (seg == 1) { src = Wk + (size_t)l * 16384; dstBase = (size_t)l * PER_L + 128 * 128; }
        else if (seg == 2) { src = Wv + (size_t)l * 16384; dstBase = (size_t)l * PER_L + 256 * 128; }
        else               { src = Wo + (size_t)l * 16384; dstBase = (size_t)l * PER_L + 49152; }
    } else if (tt < 128) {
        int local = tt - 64;
        int tk = local >> 4, tn = local & 15;
        k0 = tk * 32; n0 = tn * 32; Nn = 512; dstLd = 128;
        src = W1 + (size_t)l * 65536; dstBase = (size_t)l * PER_L + 65536;
    } else {
        int local = tt - 128;
        int tk = local >> 2, tn = local & 3;
        k0 = tk * 32; n0 = tn * 32; Nn = 128; dstLd = 512;
        src = W2 + (size_t)l * 65536; dstBase = (size_t)l * PER_L + 131072;
    }
    int tx = threadIdx.x & 31, ty = threadIdx.x >> 5;
    #pragma unroll
    for (int j = 0; j < 4; j++)
        s[ty + j * 8][tx] = src[(size_t)(k0 + ty + j * 8) * Nn + n0 + tx];
    __syncthreads();
    #pragma unroll
    for (int j = 0; j < 4; j++) {
        int n = n0 + ty + j * 8;
        float v = s[tx][ty + j * 8];
        __nv_bfloat16 hi, lo;
        split_bf16(v, hi, lo);
        size_t o = dstBase + (size_t)n * dstLd + k0 + tx;
        g_wThi[o] = hi;
        g_wTlo[o] = lo;
    }
}

// ---------------- fused LN + bf16x3 tensor-core GEMM ----------------------------
// BM=128, BN=64, K-slices of 128 resident in smem.
// AMODE: 0 = A from (Ahi,Alo) bf16 globals; 1 = LN(x,g,b); 2 = LN(x,g,b)*te
// EPI:   0 = store fp32 C; 1 = C += acc (residual); 2 = relu -> split bf16 (Chi,Clo)
#define SW 68                      // smem word stride (64 data words + 4 pad)
#define A_WORDS (128 * SW)
#define B_WORDS (64 * SW)
#define SMEMB ((2 * A_WORDS + 2 * B_WORDS) * 4)

__device__ __forceinline__ void mma_bf16(float* c, const unsigned* a, const unsigned* b) {
    asm volatile(
        "mma.sync.aligned.m16n8k16.row.col.f32.bf16.bf16.f32 "
        "{%0,%1,%2,%3}, {%4,%5,%6,%7}, {%8,%9}, {%0,%1,%2,%3};"
        : "+f"(c[0]), "+f"(c[1]), "+f"(c[2]), "+f"(c[3])
        : "r"(a[0]), "r"(a[1]), "r"(a[2]), "r"(a[3]), "r"(b[0]), "r"(b[1]));
}

template <int AMODE, int EPI>
__global__ void __launch_bounds__(256)
k_gemm(const float* __restrict__ Xf,
       const __nv_bfloat16* __restrict__ Ahi, const __nv_bfloat16* __restrict__ Alo,
       const float* __restrict__ gg, const float* __restrict__ bb,
       const __nv_bfloat16* __restrict__ Bhi, const __nv_bfloat16* __restrict__ Blo,
       float* __restrict__ C, __nv_bfloat16* __restrict__ Chi, __nv_bfloat16* __restrict__ Clo,
       int K, int Nn) {
    extern __shared__ unsigned smw[];
    unsigned* sAhi = smw;
    unsigned* sAlo = sAhi + A_WORDS;
    unsigned* sBhi = sAlo + A_WORDS;
    unsigned* sBlo = sBhi + B_WORDS;

    const int tid = threadIdx.x;
    const int lane = tid & 31, warp = tid >> 5;
    const int wm = (warp >> 1) * 32, wn = (warp & 1) * 32;
    const int g = lane >> 2, q4 = lane & 3;
    const int rowBase = blockIdx.y * 128, colBase = blockIdx.x * 64;

    float acc[2][4][4];
    #pragma unroll
    for (int mt = 0; mt < 2; mt++)
        #pragma unroll
        for (int nt = 0; nt < 4; nt++)
            #pragma unroll
            for (int i = 0; i < 4; i++) acc[mt][nt][i] = 0.0f;

    // LN params (per-lane 4 columns)
    float4 gv, bv, tv;
    if (AMODE != 0) {
        gv = *(const float4*)&gg[lane * 4];
        bv = *(const float4*)&bb[lane * 4];
        if (AMODE == 2) {
            int bIdx = rowBase / Sc;
            tv = *(const float4*)&g_te[bIdx * Dc + lane * 4];
        }
    }

    for (int kt = 0; kt < K; kt += 128) {
        if (kt) __syncthreads();
        // ---- A slice ----
        if (AMODE == 0) {
            #pragma unroll
            for (int i = 0; i < 8; i++) {
                int t = tid + i * 256;
                int r = t >> 4, c = t & 15;
                size_t goff = (size_t)(rowBase + r) * K + kt + c * 8;
                *(uint4*)&sAhi[r * SW + c * 4] = *(const uint4*)(Ahi + goff);
                *(uint4*)&sAlo[r * SW + c * 4] = *(const uint4*)(Alo + goff);
            }
        } else {
            // fused LayerNorm: warp handles 16 rows, lane covers 4 cols
            #pragma unroll
            for (int p = 0; p < 16; p++) {
                int r = warp * 16 + p;
                float4 xv = *(const float4*)&Xf[(size_t)(rowBase + r) * 128 + lane * 4];
                float s1 = xv.x + xv.y + xv.z + xv.w;
                float s2 = xv.x * xv.x + xv.y * xv.y + xv.z * xv.z + xv.w * xv.w;
                #pragma unroll
                for (int o = 16; o > 0; o >>= 1) {
                    s1 += __shfl_xor_sync(0xffffffffu, s1, o);
                    s2 += __shfl_xor_sync(0xffffffffu, s2, o);
                }
                float mean = s1 * (1.0f / 128.0f);
                float var  = s2 * (1.0f / 128.0f) - mean * mean;
                float inv  = rsqrtf(var + 1e-5f);
                float o0 = (xv.x - mean) * inv * gv.x + bv.x;
                float o1 = (xv.y - mean) * inv * gv.y + bv.y;
                float o2 = (xv.z - mean) * inv * gv.z + bv.z;
                float o3 = (xv.w - mean) * inv * gv.w + bv.w;
                if (AMODE == 2) { o0 *= tv.x; o1 *= tv.y; o2 *= tv.z; o3 *= tv.w; }
                sAhi[r * SW + lane * 2]     = pack2hi(o0, o1);
                sAhi[r * SW + lane * 2 + 1] = pack2hi(o2, o3);
                sAlo[r * SW + lane * 2]     = pack2lo(o0, o1);
                sAlo[r * SW + lane * 2 + 1] = pack2lo(o2, o3);
            }
        }
        // ---- B slice (n-major [Nn][K]) ----
        #pragma unroll
        for (int i = 0; i < 4; i++) {
            int t = tid + i * 256;
            int n = t >> 4, c = t & 15;
            size_t goff = (size_t)(colBase + n) * K + kt + c * 8;
            *(uint4*)&sBhi[n * SW + c * 4] = *(const uint4*)(Bhi + goff);
            *(uint4*)&sBlo[n * SW + c * 4] = *(const uint4*)(Blo + goff);
        }
        __syncthreads();

        #pragma unroll
        for (int ks = 0; ks < 8; ks++) {
            const int w0 = ks * 8 + q4;
            unsigned ah[2][4], al[2][4], bh[4][2], bl[4][2];
            #pragma unroll
            for (int mt = 0; mt < 2; mt++) {
                int r0 = wm + mt * 16 + g;
                ah[mt][0] = sAhi[r0 * SW + w0];
                ah[mt][1] = sAhi[(r0 + 8) * SW + w0];
                ah[mt][2] = sAhi[r0 * SW + w0 + 4];
                ah[mt][3] = sAhi[(r0 + 8) * SW + w0 + 4];
                al[mt][0] = sAlo[r0 * SW + w0];
                al[mt][1] = sAlo[(r0 + 8) * SW + w0];
                al[mt][2] = sAlo[r0 * SW + w0 + 4];
                al[mt][3] = sAlo[(r0 + 8) * SW + w0 + 4];
            }
            #pragma unroll
            for (int nt = 0; nt < 4; nt++) {
                int n0 = wn + nt * 8 + g;
                bh[nt][0] = sBhi[n0 * SW + w0];
                bh[nt][1] = sBhi[n0 * SW + w0 + 4];
                bl[nt][0] = sBlo[n0 * SW + w0];
                bl[nt][1] = sBlo[n0 * SW + w0 + 4];
            }
            #pragma unroll
            for (int mt = 0; mt < 2; mt++)
                #pragma unroll
                for (int nt = 0; nt < 4; nt++) {
                    mma_bf16(acc[mt][nt], ah[mt], bh[nt]);
                    mma_bf16(acc[mt][nt], ah[mt], bl[nt]);
                    mma_bf16(acc[mt][nt], al[mt], bh[nt]);
                }
        }
    }

    // ---- epilogue ----
    #pragma unroll
    for (int mt = 0; mt < 2; mt++)
        #pragma unroll
        for (int nt = 0; nt < 4; nt++) {
            int r = rowBase + wm + mt * 16 + g;
            int c = colBase + wn + nt * 8 + q4 * 2;
            float* a = acc[mt][nt];
            if (EPI == 0) {
                *(float2*)&C[(size_t)r * Nn + c]       = make_float2(a[0], a[1]);
                *(float2*)&C[(size_t)(r + 8) * Nn + c] = make_float2(a[2], a[3]);
            } else if (EPI == 1) {
                float2 v0 = *(const float2*)&C[(size_t)r * Nn + c];
                float2 v1 = *(const float2*)&C[(size_t)(r + 8) * Nn + c];
                v0.x += a[0]; v0.y += a[1]; v1.x += a[2]; v1.y += a[3];
                *(float2*)&C[(size_t)r * Nn + c]       = v0;
                *(float2*)&C[(size_t)(r + 8) * Nn + c] = v1;
            } else {
                #pragma unroll
                for (int rr = 0; rr < 2; rr++) {
                    float v0 = fmaxf(a[rr * 2 + 0], 0.0f);
                    float v1 = fmaxf(a[rr * 2 + 1], 0.0f);
                    size_t o = (size_t)(r + rr * 8) * Nn + c;
                    *(unsigned*)&Chi[o] = pack2hi(v0, v1);
                    *(unsigned*)&Clo[o] = pack2lo(v0, v1);
                }
            }
        }
}

// ---------------- sparse masked attention ---------------------------------------
__global__ void k_attn(const float* __restrict__ qkv,
                       __nv_bfloat16* __restrict__ ohi, __nv_bfloat16* __restrict__ olo) {
    int bs = blockIdx.x;
    int b = bs / Sc, s = bs % Sc;
    int h = threadIdx.x >> 5, lane = threadIdx.x & 31;
    int cnt = g_adjcnt[s];

    const float* qp = qkv + (size_t)bs * 384 + h * HDc;
    float qr[HDc];
    #pragma unroll
    for (int d = 0; d < HDc; d++) qr[d] = qp[d];

    float sc0 = -1e30f, sc1 = -1e30f;
    int n0 = -1, n1 = -1;
    if (lane < cnt) {
        n0 = g_adj[s * MAXNB + lane];
        const float* kp = qkv + ((size_t)b * Sc + n0) * 384 + 128 + h * HDc;
        float dot = 0.0f;
        #pragma unroll
        for (int d = 0; d < HDc; d++) dot += qr[d] * kp[d];
        sc0 = dot * 0.25f;
    }
    if (lane + 32 < cnt) {
        n1 = g_adj[s * MAXNB + lane + 32];
        const float* kp = qkv + ((size_t)b * Sc + n1) * 384 + 128 + h * HDc;
        float dot = 0.0f;
        #pragma unroll
        for (int d = 0; d < HDc; d++) dot += qr[d] * kp[d];
        sc1 = dot * 0.25f;
    }

    float m = fmaxf(sc0, sc1);
    #pragma unroll
    for (int off = 16; off > 0; off >>= 1) m = fmaxf(m, __shfl_xor_sync(0xffffffffu, m, off));
    float p0 = (n0 >= 0) ? __expf(sc0 - m) : 0.0f;
    float p1 = (n1 >= 0) ? __expf(sc1 - m) : 0.0f;
    float ps = p0 + p1;
    #pragma unroll
    for (int off = 16; off > 0; off >>= 1) ps += __shfl_xor_sync(0xffffffffu, ps, off);

    float acc[HDc] = {};
    if (n0 >= 0) {
        const float* vp = qkv + ((size_t)b * Sc + n0) * 384 + 256 + h * HDc;
        #pragma unroll
        for (int d = 0; d < HDc; d++) acc[d] += p0 * vp[d];
    }
    if (n1 >= 0) {
        const float* vp = qkv + ((size_t)b * Sc + n1) * 384 + 256 + h * HDc;
        #pragma unroll
        for (int d = 0; d < HDc; d++) acc[d] += p1 * vp[d];
    }
    #pragma unroll
    for (int d = 0; d < HDc; d++)
        #pragma unroll
        for (int off = 16; off > 0; off >>= 1)
            acc[d] += __shfl_xor_sync(0xffffffffu, acc[d], off);

    if (lane == 0) {
        float inv = 1.0f / ps;
        #pragma unroll
        for (int d = 0; d < HDc; d += 2) {
            float v0 = acc[d] * inv, v1 = acc[d + 1] * inv;
            size_t o = (size_t)bs * Dc + h * HDc + d;
            *(unsigned*)&ohi[o] = pack2hi(v0, v1);
            *(unsigned*)&olo[o] = pack2lo(v0, v1);
        }
    }
}

// ---------------- final projection ----------------------------------------------
__global__ void k_out(const float* __restrict__ fc_w, const float* __restrict__ fc_b,
                      float* __restrict__ out) {
    int row = blockIdx.x * 8 + (threadIdx.x >> 5);
    if (row >= ROWS) return;
    int lane = threadIdx.x & 31;
    float sum = 0.0f;
    #pragma unroll
    for (int d = lane; d < Dc; d += 32) sum += g_x[(size_t)row * Dc + d] * fc_w[d];
    #pragma unroll
    for (int off = 16; off > 0; off >>= 1) sum += __shfl_xor_sync(0xffffffffu, sum, off);
    if (lane == 0) out[row] = sum + fc_b[0];
}

// ---------------- launcher -------------------------------------------------------
extern "C" void kernel_launch(void* const* d_in, const int* in_sizes, int n_in,
                              void* d_out, int out_size) {
    const float* r_t        = (const float*)d_in[0];
    const int*   t          = (const int*)  d_in[1];
    const int*   pcm        = (const int*)  d_in[2];
    const float* src_embed  = (const float*)d_in[4];
    const float* time_table = (const float*)d_in[5];
    const float* Wq = (const float*)d_in[6];
    const float* Wk = (const float*)d_in[7];
    const float* Wv = (const float*)d_in[8];
    const float* Wo = (const float*)d_in[9];
    const float* W1 = (const float*)d_in[10];
    const float* W2 = (const float*)d_in[11];
    const float* g1 = (const float*)d_in[12];
    const float* b1 = (const float*)d_in[13];
    const float* g2 = (const float*)d_in[14];
    const float* b2 = (const float*)d_in[15];
    const float* fc_w = (const float*)d_in[16];
    const float* fc_b = (const float*)d_in[17];
    float* out = (float*)d_out;

    float *px, *pqkv;
    __nv_bfloat16 *whi, *wlo, *ohi, *olo, *fhi, *flo;
    cudaGetSymbolAddress((void**)&px,   g_x);
    cudaGetSymbolAddress((void**)&pqkv, g_qkv);
    cudaGetSymbolAddress((void**)&whi,  g_wThi);
    cudaGetSymbolAddress((void**)&wlo,  g_wTlo);
    cudaGetSymbolAddress((void**)&ohi,  g_ohi);
    cudaGetSymbolAddress((void**)&olo,  g_olo);
    cudaGetSymbolAddress((void**)&fhi,  g_fhi);
    cudaGetSymbolAddress((void**)&flo,  g_flo);

    static int smemSet = 0;
    if (!smemSet) {
        cudaFuncSetAttribute(k_gemm<1,0>, cudaFuncAttributeMaxDynamicSharedMemorySize, SMEMB);
        cudaFuncSetAttribute(k_gemm<0,1>, cudaFuncAttributeMaxDynamicSharedMemorySize, SMEMB);
        cudaFuncSetAttribute(k_gemm<2,2>, cudaFuncAttributeMaxDynamicSharedMemorySize, SMEMB);
        smemSet = 1;
    }

    k_te    <<<(Bc * Dc + 255) / 256, 256>>>(t, time_table);
    k_nodes <<<(Bc * Mc + 7) / 8, 256>>>(r_t, pcm);
    k_adj   <<<(Sc + 7) / 8, 256>>>(pcm);
    k_xinit <<<(ROWS * Dc + 255) / 256, 256>>>(src_embed, r_t);
    k_wsplit<<<Lc * 192, 256>>>(Wq, Wk, Wv, Wo, W1, W2);

    dim3 gQKV(6, 96);
    dim3 gD  (2, 96);
    dim3 gF  (8, 96);

    for (int l = 0; l < Lc; l++) {
        const __nv_bfloat16* lwh = whi + (size_t)l * PER_L;
        const __nv_bfloat16* lwl = wlo + (size_t)l * PER_L;

        // QKV: LN1 fused, store fp32 qkv
        k_gemm<1,0><<<gQKV, 256, SMEMB>>>(px, nullptr, nullptr, g1 + l * Dc, b1 + l * Dc,
                                          lwh, lwl, pqkv, nullptr, nullptr, 128, 384);
        k_attn<<<ROWS, 256>>>(pqkv, ohi, olo);
        // O-projection + residual
        k_gemm<0,1><<<gD, 256, SMEMB>>>(nullptr, ohi, olo, nullptr, nullptr,
                                        lwh + 49152, lwl + 49152, px, nullptr, nullptr, 128, 128);
        // W1: LN2*te fused, relu + split out
        k_gemm<2,2><<<gF, 256, SMEMB>>>(px, nullptr, nullptr, g2 + l * Dc, b2 + l * Dc,
                                        lwh + 65536, lwl + 65536, nullptr, fhi, flo, 128, 512);
        // W2 + residual (K=512)
        k_gemm<0,1><<<gD, 256, SMEMB>>>(nullptr, fhi, flo, nullptr, nullptr,
                                        lwh + 131072, lwl + 131072, px, nullptr, nullptr, 512, 128);
    }

    k_out<<<(ROWS + 7) / 8, 256>>>(fc_w, fc_b, out);
}